// round 7
// baseline (speedup 1.0000x reference)
#include <cuda_runtime.h>
#include <cuda_fp16.h>
#include <cstdint>

#define N_NODES 100000
#define M_HE    200000
#define NE      2000000
#define IN_F    16
#define HID     64
#define NT      2

#define SB (NT * M_HE)     // 400000
#define SD (NT * N_NODES)  // 200000
#define NBB ((SB + 1023) / 1024)   // 391
#define NBD ((SD + 1023) / 1024)   // 196
#define TILES ((N_NODES + 63) / 64)  // 1563
#define XW_BLOCKS (N_NODES / 16)     // 6250
#define HIST_BLOCKS ((NE + 255) / 256)

// ---------------- scratch ----------------
__device__ __align__(16) __half g_xw_h[(size_t)N_NODES * 128];
__device__ __align__(16) __half g_efeat_h[(size_t)M_HE * 128];
__device__ __align__(16) __half g_acc_h[(size_t)N_NODES * 128];
__device__ int g_hB[SB], g_hD[SD];
__device__ int g_offB[SB], g_offD[SD];
__device__ int g_curB[SB], g_curD[SD];
__device__ int g_bsum[1024];
__device__ int g_idxB[NE];
__device__ int g_idxD[NE];

// ---------------- launch 0: xw projection + histogram (block-range split) ----------------
__global__ void k_xw_hist(const float* __restrict__ x, const float* __restrict__ Wc,
                          const int* __restrict__ en, const int* __restrict__ eh,
                          const int* __restrict__ ea) {
    if (blockIdx.x < XW_BLOCKS) {
        __shared__ float Ws[NT * IN_F * HID];   // 2048
        __shared__ float xs[16 * IN_F];         // 256
        int tid = threadIdx.x;
        int n0 = blockIdx.x * 16;
        for (int i = tid; i < NT * IN_F * HID; i += 256) Ws[i] = Wc[i];
        xs[tid] = x[(size_t)n0 * IN_F + tid];
        __syncthreads();
        int c = tid & 127;
        int hf = tid >> 7;       // which 8-node group
        int t = c >> 6, cc = c & 63;
        const float* w = &Ws[t * (IN_F * HID) + cc];
        #pragma unroll
        for (int nd = 0; nd < 8; nd++) {
            int node = n0 + hf * 8 + nd;
            float a = 0.f;
            #pragma unroll
            for (int k = 0; k < IN_F; k++) a += xs[(hf * 8 + nd) * IN_F + k] * w[k * HID];
            float a_hi = __shfl_down_sync(0xffffffffu, a, 1);
            if ((c & 1) == 0) {
                __half2 hv = __floats2half2_rn(a, a_hi);
                ((__half2*)g_xw_h)[((size_t)node * 128 + c) >> 1] = hv;
            }
        }
    } else {
        int i = (blockIdx.x - XW_BLOCKS) * 256 + threadIdx.x;
        if (i >= NE) return;
        int t = ea[i];
        atomicAdd(&g_hB[t * M_HE + eh[i]], 1);
        atomicAdd(&g_hD[t * N_NODES + en[i]], 1);
    }
}

// ---------------- launch 1: per-block exclusive scan (both arrays, grid.y) ----------------
__global__ void k_scan_local() {
    int which = blockIdx.y;
    if (which == 1 && blockIdx.x >= NBD) return;
    const int n   = which ? SD : SB;
    const int* in = which ? g_hD : g_hB;
    int* out      = which ? g_offD : g_offB;
    int* sums     = g_bsum + which * 512;
    int tid = threadIdx.x;
    int base = blockIdx.x * 1024 + tid * 4;
    int v0 = (base + 0 < n) ? in[base + 0] : 0;
    int v1 = (base + 1 < n) ? in[base + 1] : 0;
    int v2 = (base + 2 < n) ? in[base + 2] : 0;
    int v3 = (base + 3 < n) ? in[base + 3] : 0;
    int s = v0 + v1 + v2 + v3;
    __shared__ int sh[256];
    sh[tid] = s;
    __syncthreads();
    for (int d = 1; d < 256; d <<= 1) {
        int v = (tid >= d) ? sh[tid - d] : 0;
        __syncthreads();
        sh[tid] += v;
        __syncthreads();
    }
    int excl = sh[tid] - s;
    if (base + 0 < n) out[base + 0] = excl;
    if (base + 1 < n) out[base + 1] = excl + v0;
    if (base + 2 < n) out[base + 2] = excl + v0 + v1;
    if (base + 3 < n) out[base + 3] = excl + v0 + v1 + v2;
    if (tid == 255) sums[blockIdx.x] = excl + s;
}

// ---------------- launch 2: scan of block sums (2 blocks) ----------------
__global__ void k_scan_tops() {
    int which = blockIdx.x;
    const int nb = which ? NBD : NBB;
    int* sums = g_bsum + which * 512;
    int tid = threadIdx.x;  // 512
    __shared__ int sh[512];
    int s = (tid < nb) ? sums[tid] : 0;
    sh[tid] = s;
    __syncthreads();
    for (int d = 1; d < 512; d <<= 1) {
        int v = (tid >= d) ? sh[tid - d] : 0;
        __syncthreads();
        sh[tid] += v;
        __syncthreads();
    }
    if (tid < nb) sums[tid] = sh[tid] - s;
}

// ---------------- launch 3: add block offsets; init cursors ----------------
__global__ void k_scan_add() {
    int which = blockIdx.y;
    const int n = which ? SD : SB;
    int* out    = which ? g_offD : g_offB;
    int* cur    = which ? g_curD : g_curB;
    const int* sums = g_bsum + which * 512;
    int i = blockIdx.x * blockDim.x + threadIdx.x;
    if (i >= n) return;
    int v = out[i] + sums[i >> 10];
    out[i] = v;
    cur[i] = v;
}

// ---------------- launch 4: placement ----------------
__global__ void k_place(const int* __restrict__ en, const int* __restrict__ eh,
                        const int* __restrict__ ea) {
    int i = blockIdx.x * blockDim.x + threadIdx.x;
    if (i >= NE) return;
    int t = ea[i], n = en[i], he = eh[i];
    int pb = atomicAdd(&g_curB[t * M_HE + he], 1);
    g_idxB[pb] = n;
    int pd = atomicAdd(&g_curD[t * N_NODES + n], 1);
    g_idxD[pd] = he;
}

__device__ __forceinline__ void accum8(float* s, uint4 v) {
    const __half2* h = (const __half2*)&v;
    #pragma unroll
    for (int i = 0; i < 4; i++) {
        float2 f = __half22float2(h[i]);
        s[2 * i]     += f.x;
        s[2 * i + 1] += f.y;
    }
}

// ---------------- launch 5: gather1 (self-zeroes g_hB for next replay) ----------------
__global__ void k_gather1() {
    int idx = blockIdx.x * blockDim.x + threadIdx.x;
    int r = idx >> 3, q = idx & 7;
    if (r >= SB) return;
    int t = (r >= M_HE) ? 1 : 0;
    int he = r - t * M_HE;
    int cnt = g_hB[r];
    int start = g_offB[r];
    if (q == 0) g_hB[r] = 0;   // same-warp lanes already read cnt (program order)
    const uint4* xw4 = (const uint4*)g_xw_h;
    int off = t * 8 + q;
    float s[8] = {0.f, 0.f, 0.f, 0.f, 0.f, 0.f, 0.f, 0.f};
    int j = 0;
    for (; j + 2 <= cnt; j += 2) {
        int n0 = __ldg(&g_idxB[start + j]);
        int n1 = __ldg(&g_idxB[start + j + 1]);
        uint4 v0 = xw4[(size_t)n0 * 16 + off];
        uint4 v1 = xw4[(size_t)n1 * 16 + off];
        accum8(s, v0);
        accum8(s, v1);
    }
    if (j < cnt) {
        int n = __ldg(&g_idxB[start + j]);
        accum8(s, xw4[(size_t)n * 16 + off]);
    }
    float binv = (cnt > 0) ? (1.f / (float)cnt) : 0.f;
    uint4 outv;
    __half2* oh = (__half2*)&outv;
    #pragma unroll
    for (int i = 0; i < 4; i++)
        oh[i] = __floats2half2_rn(s[2 * i] * binv, s[2 * i + 1] * binv);
    ((uint4*)g_efeat_h)[(size_t)he * 16 + t * 8 + q] = outv;
}

// ---------------- launch 6: gather2 (fp16 out; self-zeroes g_hD) ----------------
__global__ void k_gather2() {
    int idx = blockIdx.x * blockDim.x + threadIdx.x;
    int r = idx >> 3, q = idx & 7;
    if (r >= SD) return;
    int t = (r >= N_NODES) ? 1 : 0;
    int n = r - t * N_NODES;
    int cnt = g_hD[r];
    int start = g_offD[r];
    if (q == 0) g_hD[r] = 0;
    const uint4* ef4 = (const uint4*)g_efeat_h;
    int off = t * 8 + q;
    float s[8] = {0.f, 0.f, 0.f, 0.f, 0.f, 0.f, 0.f, 0.f};
    int j = 0;
    for (; j + 2 <= cnt; j += 2) {
        int h0 = __ldg(&g_idxD[start + j]);
        int h1 = __ldg(&g_idxD[start + j + 1]);
        uint4 v0 = ef4[(size_t)h0 * 16 + off];
        uint4 v1 = ef4[(size_t)h1 * 16 + off];
        accum8(s, v0);
        accum8(s, v1);
    }
    if (j < cnt) {
        int he = __ldg(&g_idxD[start + j]);
        accum8(s, ef4[(size_t)he * 16 + off]);
    }
    float dinv = (cnt > 0) ? (1.f / (float)cnt) : 0.f;
    uint4 outv;
    __half2* oh = (__half2*)&outv;
    #pragma unroll
    for (int i = 0; i < 4; i++)
        oh[i] = __floats2half2_rn(s[2 * i] * dinv, s[2 * i + 1] * dinv);
    ((uint4*)g_acc_h)[(size_t)n * 16 + t * 8 + q] = outv;
}

__device__ __forceinline__ float sigf(float x) { return 1.f / (1.f + expf(-x)); }

#define MMA16816(c0, c1, c2, c3, a0, a1, a2, a3, b0, b1) \
    asm volatile("mma.sync.aligned.m16n8k16.row.col.f32.f16.f16.f32 " \
                 "{%0,%1,%2,%3}, {%4,%5,%6,%7}, {%8,%9}, {%0,%1,%2,%3};" \
                 : "+f"(c0), "+f"(c1), "+f"(c2), "+f"(c3) \
                 : "r"(a0), "r"(a1), "r"(a2), "r"(a3), "r"(b0), "r"(b1))

// ---------------- launch 7: fused mix + GRU + output (persistent MMA) ----------------
// smem (floats):
//   [0, 25088)       stage gi/gh [2][64][196]; ALIASED with:
//                      init:  Wih16 [192][72]h | Whh16 [192][72]h | WmixT [64][136]h
//                      tile:  u16 [64][136]h (dead before stage written)
//   [25088, 27392)   h16  [64][72] halves
//   [27392, 29696)   hp16 [64][72] halves
//   [29696, 34048)   hnS  [64][68] floats
//   [34048, ...]     bihS 192 | bhhS 192 | woS 192 | boS 4 | bmixS 64 | bcS 128
__global__ __launch_bounds__(256, 1)
void k_gru_fused(const float* __restrict__ hprev,
                 const float* __restrict__ Wmix, const float* __restrict__ bmix,
                 const float* __restrict__ bconv,
                 const float* __restrict__ Wih, const float* __restrict__ Whh,
                 const float* __restrict__ bih, const float* __restrict__ bhh,
                 const float* __restrict__ Wout, const float* __restrict__ bout,
                 float* __restrict__ out_h, float* __restrict__ out_p) {
    extern __shared__ float smf[];
    float*  stage = smf;
    __half* u16   = (__half*)smf;                 // [64][136]
    __half* Wih16 = (__half*)smf;                 // [192][72]
    __half* Whh16 = Wih16 + 192 * 72;
    __half* WmixT = Whh16 + 192 * 72;             // [64][136]
    __half* h16   = (__half*)(smf + 25088);       // [64][72]
    __half* hp16  = h16 + 64 * 72;
    float*  hnS   = smf + 29696;
    float*  bihS  = smf + 34048;
    float*  bhhS  = bihS + 192;
    float*  woS   = bhhS + 192;
    float*  boS   = woS + 192;
    float*  bmixS = boS + 4;
    float*  bcS   = bmixS + 64;

    int tid = threadIdx.x;
    int lane = tid & 31;
    int wrp = tid >> 5;
    int g = lane >> 2;
    int t = lane & 3;
    int cbase = wrp * 24;

    if (tid < 192) {
        bihS[tid] = bih[tid];
        bhhS[tid] = bhh[tid];
        int j = tid / 3, k = tid % 3;
        woS[tid] = Wout[j * 64 + k];
    }
    if (tid < 3)   boS[tid] = bout[tid];
    if (tid < 64)  bmixS[tid] = bmix[tid];
    if (tid < 128) bcS[tid] = bconv[tid];

    for (int i = tid; i < 192 * 64; i += 256) {
        int r = i >> 6, k = i & 63;
        Wih16[r * 72 + k] = __float2half(Wih[i]);
        Whh16[r * 72 + k] = __float2half(Whh[i]);
    }
    for (int i = tid; i < 64 * 128; i += 256) {
        int n = i >> 7, k = i & 127;
        WmixT[n * 136 + k] = __float2half(Wmix[k * 64 + n]);
    }
    __syncthreads();

    // B fragments: GRU (3 gate-tiles x 4 ksteps) and mix (8 ksteps)
    uint32_t Bi[3][4][2], Bh[3][4][2], Bm[8][2];
    #pragma unroll
    for (int nt = 0; nt < 3; nt++) {
        int n = cbase + nt * 8 + g;
        #pragma unroll
        for (int ks = 0; ks < 4; ks++) {
            Bi[nt][ks][0] = *(const uint32_t*)&Wih16[n * 72 + ks * 16 + 2 * t];
            Bi[nt][ks][1] = *(const uint32_t*)&Wih16[n * 72 + ks * 16 + 2 * t + 8];
            Bh[nt][ks][0] = *(const uint32_t*)&Whh16[n * 72 + ks * 16 + 2 * t];
            Bh[nt][ks][1] = *(const uint32_t*)&Whh16[n * 72 + ks * 16 + 2 * t + 8];
        }
    }
    {
        int nbm = wrp * 8 + g;
        #pragma unroll
        for (int ks = 0; ks < 8; ks++) {
            Bm[ks][0] = *(const uint32_t*)&WmixT[nbm * 136 + ks * 16 + 2 * t];
            Bm[ks][1] = *(const uint32_t*)&WmixT[nbm * 136 + ks * 16 + 2 * t + 8];
        }
    }
    __syncthreads();   // W smem dead

    for (int tile = blockIdx.x; tile < TILES; tile += gridDim.x) {
        int n0 = tile * 64;
        // build u16 = acc + b_conv, load hp16
        for (int i = tid; i < 64 * 128; i += 256) {
            int nd = i >> 7, c = i & 127;
            int n = n0 + nd;
            float u = 0.f;
            if (n < N_NODES) u = __half2float(g_acc_h[(size_t)n * 128 + c]) + bcS[c];
            u16[nd * 136 + c] = __float2half(u);
        }
        for (int i = tid; i < 64 * 64; i += 256) {
            int nd = i >> 6, k = i & 63;
            int n = n0 + nd;
            float pv = (n < N_NODES) ? hprev[(size_t)n * 64 + k] : 0.f;
            hp16[nd * 72 + k] = __float2half(pv);
        }
        __syncthreads();

        // ---- mix MMA: h = relu(u @ Wmix + bmix) -> h16 ----
        {
            float am[4][4];
            #pragma unroll
            for (int m = 0; m < 4; m++)
                #pragma unroll
                for (int c = 0; c < 4; c++) am[m][c] = 0.f;
            #pragma unroll
            for (int ks = 0; ks < 8; ks++) {
                #pragma unroll
                for (int m = 0; m < 4; m++) {
                    int row = m * 16 + g;
                    int ko = ks * 16 + 2 * t;
                    uint32_t a0 = *(const uint32_t*)&u16[row * 136 + ko];
                    uint32_t a1 = *(const uint32_t*)&u16[(row + 8) * 136 + ko];
                    uint32_t a2 = *(const uint32_t*)&u16[row * 136 + ko + 8];
                    uint32_t a3 = *(const uint32_t*)&u16[(row + 8) * 136 + ko + 8];
                    MMA16816(am[m][0], am[m][1], am[m][2], am[m][3],
                             a0, a1, a2, a3, Bm[ks][0], Bm[ks][1]);
                }
            }
            __syncthreads();   // all u16 reads done before h16 write? (different region; sync for stage aliasing later)
            int col = wrp * 8 + 2 * t;
            #pragma unroll
            for (int m = 0; m < 4; m++) {
                int row = m * 16 + g;
                float h0 = fmaxf(am[m][0] + bmixS[col], 0.f);
                float h1 = fmaxf(am[m][1] + bmixS[col + 1], 0.f);
                float h2 = fmaxf(am[m][2] + bmixS[col], 0.f);
                float h3 = fmaxf(am[m][3] + bmixS[col + 1], 0.f);
                *(__half2*)&h16[row * 72 + col]       = __floats2half2_rn(h0, h1);
                *(__half2*)&h16[(row + 8) * 72 + col] = __floats2half2_rn(h2, h3);
            }
        }
        __syncthreads();

        // ---- GRU MMA ----
        float acc[2][4][3][4];
        #pragma unroll
        for (int mt = 0; mt < 2; mt++)
            #pragma unroll
            for (int m = 0; m < 4; m++)
                #pragma unroll
                for (int nt = 0; nt < 3; nt++)
                    #pragma unroll
                    for (int c = 0; c < 4; c++) acc[mt][m][nt][c] = 0.f;

        #pragma unroll
        for (int mt = 0; mt < 2; mt++) {
            const __half* A = mt ? hp16 : h16;
            #pragma unroll
            for (int ks = 0; ks < 4; ks++) {
                #pragma unroll
                for (int m = 0; m < 4; m++) {
                    int row = m * 16 + g;
                    int ko = ks * 16 + 2 * t;
                    uint32_t a0 = *(const uint32_t*)&A[row * 72 + ko];
                    uint32_t a1 = *(const uint32_t*)&A[(row + 8) * 72 + ko];
                    uint32_t a2 = *(const uint32_t*)&A[row * 72 + ko + 8];
                    uint32_t a3 = *(const uint32_t*)&A[(row + 8) * 72 + ko + 8];
                    #pragma unroll
                    for (int nt = 0; nt < 3; nt++) {
                        if (mt == 0) {
                            MMA16816(acc[0][m][nt][0], acc[0][m][nt][1],
                                     acc[0][m][nt][2], acc[0][m][nt][3],
                                     a0, a1, a2, a3, Bi[nt][ks][0], Bi[nt][ks][1]);
                        } else {
                            MMA16816(acc[1][m][nt][0], acc[1][m][nt][1],
                                     acc[1][m][nt][2], acc[1][m][nt][3],
                                     a0, a1, a2, a3, Bh[nt][ks][0], Bh[nt][ks][1]);
                        }
                    }
                }
            }
        }

        // stage gi/gh to smem (overwrites u16 area — u16 dead)
        #pragma unroll
        for (int mt = 0; mt < 2; mt++) {
            float* st = stage + mt * 12544;
            #pragma unroll
            for (int m = 0; m < 4; m++) {
                int row = m * 16 + g;
                #pragma unroll
                for (int nt = 0; nt < 3; nt++) {
                    int col = cbase + nt * 8 + 2 * t;
                    *(float2*)&st[row * 196 + col] =
                        make_float2(acc[mt][m][nt][0], acc[mt][m][nt][1]);
                    *(float2*)&st[(row + 8) * 196 + col] =
                        make_float2(acc[mt][m][nt][2], acc[mt][m][nt][3]);
                }
            }
        }
        __syncthreads();

        // gates
        for (int i = tid; i < 64 * 64; i += 256) {
            int nd = i >> 6, j = i & 63;
            int n = n0 + nd;
            float ir = stage[nd * 196 + j]        + bihS[j];
            float iz = stage[nd * 196 + j + 64]   + bihS[64 + j];
            float in_ = stage[nd * 196 + j + 128] + bihS[128 + j];
            float hr = stage[12544 + nd * 196 + j]       + bhhS[j];
            float hz = stage[12544 + nd * 196 + j + 64]  + bhhS[64 + j];
            float hn = stage[12544 + nd * 196 + j + 128] + bhhS[128 + j];
            float hp = (n < N_NODES) ? hprev[(size_t)n * 64 + j] : 0.f;
            float r = sigf(ir + hr);
            float z = sigf(iz + hz);
            float nn = tanhf(in_ + r * hn);
            float hx = (1.f - z) * nn + z * hp;
            if (n < N_NODES) out_h[(size_t)n * 64 + j] = hx;
            hnS[nd * 68 + j] = hx;
        }
        __syncthreads();

        if (tid < 192) {
            int nd = tid / 3, k = tid % 3;
            int n = n0 + nd;
            if (n < N_NODES) {
                float a = boS[k];
                #pragma unroll
                for (int j = 0; j < 64; j++) a += hnS[nd * 68 + j] * woS[j * 3 + k];
                out_p[(size_t)n * 3 + k] = a;
            }
        }
        __syncthreads();
    }
}

extern "C" void kernel_launch(void* const* d_in, const int* in_sizes, int n_in,
                              void* d_out, int out_size) {
    const float* x       = (const float*)d_in[0];
    const float* h_prev  = (const float*)d_in[1];
    const int* en        = (const int*)d_in[2];
    const int* eh        = (const int*)d_in[3];
    const int* ea        = (const int*)d_in[4];
    const float* W_conv  = (const float*)d_in[5];
    const float* b_conv  = (const float*)d_in[6];
    const float* W_mix   = (const float*)d_in[7];
    const float* b_mix   = (const float*)d_in[8];
    const float* W_ih    = (const float*)d_in[9];
    const float* W_hh    = (const float*)d_in[10];
    const float* b_ih    = (const float*)d_in[11];
    const float* b_hh    = (const float*)d_in[12];
    const float* W_out   = (const float*)d_in[13];
    const float* b_out   = (const float*)d_in[14];
    float* out = (float*)d_out;
    float* out_h = out;
    float* out_p = out + (size_t)N_NODES * 64;

    static const int gru_smem = (34048 + 192 * 3 + 4 + 64 + 128) * 4;
    cudaFuncSetAttribute(k_gru_fused, cudaFuncAttributeMaxDynamicSharedMemorySize, gru_smem);

    k_xw_hist<<<XW_BLOCKS + HIST_BLOCKS, 256>>>(x, W_conv, en, eh, ea);   // 0
    k_scan_local<<<dim3(NBB, 2), 256>>>();                                 // 1
    k_scan_tops<<<2, 512>>>();                                             // 2
    k_scan_add<<<dim3((SB + 255) / 256, 2), 256>>>();                      // 3
    k_place<<<(NE + 255) / 256, 256>>>(en, eh, ea);                        // 4
    k_gather1<<<(SB * 8 + 255) / 256, 256>>>();                            // 5  <- ncu sample
    k_gather2<<<(SD * 8 + 255) / 256, 256>>>();                            // 6
    k_gru_fused<<<152, 256, gru_smem>>>(h_prev, W_mix, b_mix, b_conv,      // 7
                                        W_ih, W_hh, b_ih, b_hh,
                                        W_out, b_out, out_h, out_p);
}

// round 8
// speedup vs baseline: 1.1955x; 1.1955x over previous
#include <cuda_runtime.h>
#include <cuda_fp16.h>
#include <cstdint>

#define N_NODES 100000
#define M_HE    200000
#define NE      2000000
#define IN_F    16
#define HID     64
#define NT      2

#define SB (NT * M_HE)     // 400000
#define SD (NT * N_NODES)  // 200000
#define NBB ((SB + 1023) / 1024)   // 391
#define NBD ((SD + 1023) / 1024)   // 196
#define TILES ((N_NODES + 63) / 64)  // 1563

// ---------------- scratch ----------------
__device__ __align__(16) __half g_xw_h[(size_t)N_NODES * 128];
__device__ __align__(16) __half g_efeat_h[(size_t)M_HE * 128];
__device__ __align__(16) float  g_acc[(size_t)N_NODES * 128];
__device__ __align__(16) float  g_h[(size_t)N_NODES * HID];
__device__ int g_hB[SB], g_hD[SD];
__device__ int g_offB[SB], g_offD[SD];
__device__ int g_curB[SB], g_curD[SD];
__device__ int g_bsum[1024];
__device__ int g_idxB[NE];
__device__ int g_idxD[NE];

// ---------------- zero histograms ----------------
__global__ void k_zero_hist() {
    int i = blockIdx.x * blockDim.x + threadIdx.x;
    if (i < SB) g_hB[i] = 0;
    if (i < SD) g_hD[i] = 0;
}

// ---------------- histogram ----------------
__global__ void k_hist(const int* __restrict__ en, const int* __restrict__ eh,
                       const int* __restrict__ ea) {
    int i = blockIdx.x * blockDim.x + threadIdx.x;
    if (i >= NE) return;
    int t = ea[i];
    atomicAdd(&g_hB[t * M_HE + eh[i]], 1);
    atomicAdd(&g_hD[t * N_NODES + en[i]], 1);
}

// ---------------- scan step 1 ----------------
__global__ void k_scan_local(int which) {
    const int n   = which ? SD : SB;
    const int* in = which ? g_hD : g_hB;
    int* out      = which ? g_offD : g_offB;
    int* sums     = g_bsum + which * 512;
    int tid = threadIdx.x;
    int base = blockIdx.x * 1024 + tid * 4;
    int v0 = (base + 0 < n) ? in[base + 0] : 0;
    int v1 = (base + 1 < n) ? in[base + 1] : 0;
    int v2 = (base + 2 < n) ? in[base + 2] : 0;
    int v3 = (base + 3 < n) ? in[base + 3] : 0;
    int s = v0 + v1 + v2 + v3;
    __shared__ int sh[256];
    sh[tid] = s;
    __syncthreads();
    for (int d = 1; d < 256; d <<= 1) {
        int v = (tid >= d) ? sh[tid - d] : 0;
        __syncthreads();
        sh[tid] += v;
        __syncthreads();
    }
    int excl = sh[tid] - s;
    if (base + 0 < n) out[base + 0] = excl;
    if (base + 1 < n) out[base + 1] = excl + v0;
    if (base + 2 < n) out[base + 2] = excl + v0 + v1;
    if (base + 3 < n) out[base + 3] = excl + v0 + v1 + v2;
    if (tid == 255) sums[blockIdx.x] = excl + s;
}

// ---------------- scan step 2 ----------------
__global__ void k_scan_tops(int which) {
    const int nb = which ? NBD : NBB;
    int* sums = g_bsum + which * 512;
    int tid = threadIdx.x;  // 512
    __shared__ int sh[512];
    int s = (tid < nb) ? sums[tid] : 0;
    sh[tid] = s;
    __syncthreads();
    for (int d = 1; d < 512; d <<= 1) {
        int v = (tid >= d) ? sh[tid - d] : 0;
        __syncthreads();
        sh[tid] += v;
        __syncthreads();
    }
    if (tid < nb) sums[tid] = sh[tid] - s;
}

// ---------------- scan step 3 ----------------
__global__ void k_scan_add(int which) {
    const int n = which ? SD : SB;
    int* out    = which ? g_offD : g_offB;
    int* cur    = which ? g_curD : g_curB;
    const int* sums = g_bsum + which * 512;
    int i = blockIdx.x * blockDim.x + threadIdx.x;
    if (i >= n) return;
    int v = out[i] + sums[i >> 10];
    out[i] = v;
    cur[i] = v;
}

// ---------------- placement ----------------
__global__ void k_place(const int* __restrict__ en, const int* __restrict__ eh,
                        const int* __restrict__ ea) {
    int i = blockIdx.x * blockDim.x + threadIdx.x;
    if (i >= NE) return;
    int t = ea[i], n = en[i], he = eh[i];
    int pb = atomicAdd(&g_curB[t * M_HE + he], 1);
    g_idxB[pb] = n;
    int pd = atomicAdd(&g_curD[t * N_NODES + n], 1);
    g_idxD[pd] = he;
}

// ---------------- xw = x @ W_conv[t] (fp16 out) ----------------
__global__ void k_xw(const float* __restrict__ x, const float* __restrict__ Wc) {
    __shared__ float Ws[NT * IN_F * HID];
    __shared__ float xs[8 * IN_F];
    int tid = threadIdx.x;
    int n0 = blockIdx.x * 8;
    #pragma unroll
    for (int i = tid; i < NT * IN_F * HID; i += 128) Ws[i] = Wc[i];
    xs[tid] = x[(size_t)n0 * IN_F + tid];
    __syncthreads();
    int c = tid;
    int t = c >> 6, cc = c & 63;
    const float* w = &Ws[t * (IN_F * HID) + cc];
    #pragma unroll
    for (int nd = 0; nd < 8; nd++) {
        float a = 0.f;
        #pragma unroll
        for (int k = 0; k < IN_F; k++) a += xs[nd * IN_F + k] * w[k * HID];
        float a_hi = __shfl_down_sync(0xffffffffu, a, 1);
        if ((c & 1) == 0) {
            __half2 hv = __floats2half2_rn(a, a_hi);
            ((__half2*)g_xw_h)[((size_t)(n0 + nd) * 128 + c) >> 1] = hv;
        }
    }
}

__device__ __forceinline__ void accum8(float* s, uint4 v) {
    const __half2* h = (const __half2*)&v;
    #pragma unroll
    for (int i = 0; i < 4; i++) {
        float2 f = __half22float2(h[i]);
        s[2 * i]     += f.x;
        s[2 * i + 1] += f.y;
    }
}

// ---------------- gather 1 (unroll-4) ----------------
__global__ void k_gather1() {
    int idx = blockIdx.x * blockDim.x + threadIdx.x;
    int r = idx >> 3, q = idx & 7;
    if (r >= SB) return;
    int t = (r >= M_HE) ? 1 : 0;
    int he = r - t * M_HE;
    int cnt = g_hB[r];
    int start = g_offB[r];
    const uint4* xw4 = (const uint4*)g_xw_h;
    int off = t * 8 + q;
    float s[8] = {0.f, 0.f, 0.f, 0.f, 0.f, 0.f, 0.f, 0.f};
    int j = 0;
    for (; j + 4 <= cnt; j += 4) {
        int n0 = __ldg(&g_idxB[start + j]);
        int n1 = __ldg(&g_idxB[start + j + 1]);
        int n2 = __ldg(&g_idxB[start + j + 2]);
        int n3 = __ldg(&g_idxB[start + j + 3]);
        uint4 v0 = xw4[(size_t)n0 * 16 + off];
        uint4 v1 = xw4[(size_t)n1 * 16 + off];
        uint4 v2 = xw4[(size_t)n2 * 16 + off];
        uint4 v3 = xw4[(size_t)n3 * 16 + off];
        accum8(s, v0); accum8(s, v1); accum8(s, v2); accum8(s, v3);
    }
    for (; j < cnt; j++) {
        int n = __ldg(&g_idxB[start + j]);
        accum8(s, xw4[(size_t)n * 16 + off]);
    }
    float binv = (cnt > 0) ? (1.f / (float)cnt) : 0.f;
    uint4 outv;
    __half2* oh = (__half2*)&outv;
    #pragma unroll
    for (int i = 0; i < 4; i++)
        oh[i] = __floats2half2_rn(s[2 * i] * binv, s[2 * i + 1] * binv);
    ((uint4*)g_efeat_h)[(size_t)he * 16 + t * 8 + q] = outv;
}

// ---------------- gather 2 (unroll-4, fp32 out) ----------------
__global__ void k_gather2() {
    int idx = blockIdx.x * blockDim.x + threadIdx.x;
    int r = idx >> 3, q = idx & 7;
    if (r >= SD) return;
    int t = (r >= N_NODES) ? 1 : 0;
    int n = r - t * N_NODES;
    int cnt = g_hD[r];
    int start = g_offD[r];
    const uint4* ef4 = (const uint4*)g_efeat_h;
    int off = t * 8 + q;
    float s[8] = {0.f, 0.f, 0.f, 0.f, 0.f, 0.f, 0.f, 0.f};
    int j = 0;
    for (; j + 4 <= cnt; j += 4) {
        int h0 = __ldg(&g_idxD[start + j]);
        int h1 = __ldg(&g_idxD[start + j + 1]);
        int h2 = __ldg(&g_idxD[start + j + 2]);
        int h3 = __ldg(&g_idxD[start + j + 3]);
        uint4 v0 = ef4[(size_t)h0 * 16 + off];
        uint4 v1 = ef4[(size_t)h1 * 16 + off];
        uint4 v2 = ef4[(size_t)h2 * 16 + off];
        uint4 v3 = ef4[(size_t)h3 * 16 + off];
        accum8(s, v0); accum8(s, v1); accum8(s, v2); accum8(s, v3);
    }
    for (; j < cnt; j++) {
        int he = __ldg(&g_idxD[start + j]);
        accum8(s, ef4[(size_t)he * 16 + off]);
    }
    float dinv = (cnt > 0) ? (1.f / (float)cnt) : 0.f;
    float4 o0 = make_float4(s[0] * dinv, s[1] * dinv, s[2] * dinv, s[3] * dinv);
    float4 o1 = make_float4(s[4] * dinv, s[5] * dinv, s[6] * dinv, s[7] * dinv);
    ((float4*)g_acc)[(size_t)n * 32 + t * 16 + q * 2]     = o0;
    ((float4*)g_acc)[(size_t)n * 32 + t * 16 + q * 2 + 1] = o1;
}

#define FMA2(d, a, b) asm("fma.rn.f32x2 %0, %1, %2, %0;" : "+l"(d) : "l"(a), "l"(b))

__device__ __forceinline__ float hsum2(uint64_t v) {
    float lo, hi;
    asm("mov.b64 {%0,%1}, %2;" : "=f"(lo), "=f"(hi) : "l"(v));
    return lo + hi;
}

// ---------------- mix ----------------
__global__ void k_mix(const float* __restrict__ Wmix, const float* __restrict__ bmix,
                      const float* __restrict__ bconv) {
    extern __shared__ float sm[];
    float* u_s  = sm;                 // 64 * 130
    float* Wp   = sm + 8320;          // 8192
    float* bm_s = Wp + 8192;          // 64
    float* bc_s = bm_s + 64;          // 128
    int tid = threadIdx.x;
    int n0 = blockIdx.x * 64;

    for (int i = tid; i < 4096; i += 256) {
        int k2 = i >> 6, c = i & 63;
        Wp[i * 2]     = Wmix[(2 * k2) * 64 + c];
        Wp[i * 2 + 1] = Wmix[(2 * k2 + 1) * 64 + c];
    }
    if (tid < 64)  bm_s[tid] = bmix[tid];
    if (tid < 128) bc_s[tid] = bconv[tid];
    __syncthreads();

    for (int idx = tid; idx < 64 * 128; idx += 256) {
        int nd = idx >> 7, c = idx & 127;
        int n = n0 + nd;
        float u = 0.f;
        if (n < N_NODES) u = g_acc[(size_t)n * 128 + c] + bc_s[c];
        u_s[nd * 130 + c] = u;
    }
    __syncthreads();

    int colg = tid & 15;
    int nodeg = tid >> 4;
    uint64_t acc2[4][4];
    #pragma unroll
    for (int i = 0; i < 4; i++)
        #pragma unroll
        for (int j = 0; j < 4; j++) acc2[i][j] = 0ull;

    #pragma unroll 4
    for (int k2 = 0; k2 < 64; k2++) {
        uint64_t w[4];
        #pragma unroll
        for (int j = 0; j < 4; j++)
            w[j] = *(const uint64_t*)&Wp[(k2 * 64 + colg + 16 * j) * 2];
        #pragma unroll
        for (int i = 0; i < 4; i++) {
            uint64_t uv = *(const uint64_t*)&u_s[(nodeg * 4 + i) * 130 + k2 * 2];
            #pragma unroll
            for (int j = 0; j < 4; j++) FMA2(acc2[i][j], uv, w[j]);
        }
    }

    #pragma unroll
    for (int i = 0; i < 4; i++) {
        int n = n0 + nodeg * 4 + i;
        if (n < N_NODES) {
            #pragma unroll
            for (int j = 0; j < 4; j++) {
                int col = colg + 16 * j;
                float h = hsum2(acc2[i][j]) + bm_s[col];
                g_h[(size_t)n * 64 + col] = fmaxf(h, 0.f);
            }
        }
    }
}

__device__ __forceinline__ float sigf(float x) { return 1.f / (1.f + expf(-x)); }

#define MMA16816(c0, c1, c2, c3, a0, a1, a2, a3, b0, b1) \
    asm volatile("mma.sync.aligned.m16n8k16.row.col.f32.f16.f16.f32 " \
                 "{%0,%1,%2,%3}, {%4,%5,%6,%7}, {%8,%9}, {%0,%1,%2,%3};" \
                 : "+f"(c0), "+f"(c1), "+f"(c2), "+f"(c3) \
                 : "r"(a0), "r"(a1), "r"(a2), "r"(a3), "r"(b0), "r"(b1))

// ---------------- GRU via fp16 mma.sync (persistent) ----------------
__global__ __launch_bounds__(256, 1)
void k_gru_mma(const float* __restrict__ hprev,
               const float* __restrict__ Wih, const float* __restrict__ Whh,
               const float* __restrict__ bih, const float* __restrict__ bhh,
               const float* __restrict__ Wout, const float* __restrict__ bout,
               float* __restrict__ out_h, float* __restrict__ out_p) {
    extern __shared__ float smf[];
    float*  stage = smf;                          // [2][64][196]
    __half* Wih16 = (__half*)smf;                 // [192][72]
    __half* Whh16 = Wih16 + 192 * 72;             // [192][72]
    __half* h16   = (__half*)(smf + 25088);       // [64][72]
    __half* hp16  = h16 + 64 * 72;                // [64][72]
    float*  hnS   = smf + 29696;                  // [64][68]
    float*  bihS  = smf + 34048;
    float*  bhhS  = bihS + 192;
    float*  woS   = bhhS + 192;
    float*  boS   = woS + 192;

    int tid = threadIdx.x;
    int lane = tid & 31;
    int wrp = tid >> 5;
    int g = lane >> 2;
    int t = lane & 3;
    int cbase = wrp * 24;

    if (tid < 192) {
        bihS[tid] = bih[tid];
        bhhS[tid] = bhh[tid];
        int j = tid / 3, k = tid % 3;
        woS[tid] = Wout[j * 64 + k];
    }
    if (tid < 3) boS[tid] = bout[tid];

    for (int i = tid; i < 192 * 64; i += 256) {
        int r = i >> 6, k = i & 63;
        Wih16[r * 72 + k] = __float2half(Wih[i]);
        Whh16[r * 72 + k] = __float2half(Whh[i]);
    }
    __syncthreads();

    uint32_t Bi[3][4][2], Bh[3][4][2];
    #pragma unroll
    for (int nt = 0; nt < 3; nt++) {
        int n = cbase + nt * 8 + g;
        #pragma unroll
        for (int ks = 0; ks < 4; ks++) {
            Bi[nt][ks][0] = *(const uint32_t*)&Wih16[n * 72 + ks * 16 + 2 * t];
            Bi[nt][ks][1] = *(const uint32_t*)&Wih16[n * 72 + ks * 16 + 2 * t + 8];
            Bh[nt][ks][0] = *(const uint32_t*)&Whh16[n * 72 + ks * 16 + 2 * t];
            Bh[nt][ks][1] = *(const uint32_t*)&Whh16[n * 72 + ks * 16 + 2 * t + 8];
        }
    }
    __syncthreads();

    for (int tile = blockIdx.x; tile < TILES; tile += gridDim.x) {
        int n0 = tile * 64;
        for (int i = tid; i < 64 * 64; i += 256) {
            int nd = i >> 6, k = i & 63;
            int n = n0 + nd;
            float hv = 0.f, pv = 0.f;
            if (n < N_NODES) {
                hv = g_h[(size_t)n * 64 + k];
                pv = hprev[(size_t)n * 64 + k];
            }
            h16[nd * 72 + k]  = __float2half(hv);
            hp16[nd * 72 + k] = __float2half(pv);
        }
        __syncthreads();

        float acc[2][4][3][4];
        #pragma unroll
        for (int mt = 0; mt < 2; mt++)
            #pragma unroll
            for (int m = 0; m < 4; m++)
                #pragma unroll
                for (int nt = 0; nt < 3; nt++)
                    #pragma unroll
                    for (int c = 0; c < 4; c++) acc[mt][m][nt][c] = 0.f;

        #pragma unroll
        for (int mt = 0; mt < 2; mt++) {
            const __half* A = mt ? hp16 : h16;
            #pragma unroll
            for (int ks = 0; ks < 4; ks++) {
                #pragma unroll
                for (int m = 0; m < 4; m++) {
                    int row = m * 16 + g;
                    int ko = ks * 16 + 2 * t;
                    uint32_t a0 = *(const uint32_t*)&A[row * 72 + ko];
                    uint32_t a1 = *(const uint32_t*)&A[(row + 8) * 72 + ko];
                    uint32_t a2 = *(const uint32_t*)&A[row * 72 + ko + 8];
                    uint32_t a3 = *(const uint32_t*)&A[(row + 8) * 72 + ko + 8];
                    #pragma unroll
                    for (int nt = 0; nt < 3; nt++) {
                        if (mt == 0) {
                            MMA16816(acc[0][m][nt][0], acc[0][m][nt][1],
                                     acc[0][m][nt][2], acc[0][m][nt][3],
                                     a0, a1, a2, a3, Bi[nt][ks][0], Bi[nt][ks][1]);
                        } else {
                            MMA16816(acc[1][m][nt][0], acc[1][m][nt][1],
                                     acc[1][m][nt][2], acc[1][m][nt][3],
                                     a0, a1, a2, a3, Bh[nt][ks][0], Bh[nt][ks][1]);
                        }
                    }
                }
            }
        }

        #pragma unroll
        for (int mt = 0; mt < 2; mt++) {
            float* st = stage + mt * 12544;
            #pragma unroll
            for (int m = 0; m < 4; m++) {
                int row = m * 16 + g;
                #pragma unroll
                for (int nt = 0; nt < 3; nt++) {
                    int col = cbase + nt * 8 + 2 * t;
                    *(float2*)&st[row * 196 + col] =
                        make_float2(acc[mt][m][nt][0], acc[mt][m][nt][1]);
                    *(float2*)&st[(row + 8) * 196 + col] =
                        make_float2(acc[mt][m][nt][2], acc[mt][m][nt][3]);
                }
            }
        }
        __syncthreads();

        for (int i = tid; i < 64 * 64; i += 256) {
            int nd = i >> 6, j = i & 63;
            int n = n0 + nd;
            float ir = stage[nd * 196 + j]        + bihS[j];
            float iz = stage[nd * 196 + j + 64]   + bihS[64 + j];
            float in_ = stage[nd * 196 + j + 128] + bihS[128 + j];
            float hr = stage[12544 + nd * 196 + j]        + bhhS[j];
            float hz = stage[12544 + nd * 196 + j + 64]   + bhhS[64 + j];
            float hn = stage[12544 + nd * 196 + j + 128]  + bhhS[128 + j];
            float hp = (n < N_NODES) ? hprev[(size_t)n * 64 + j] : 0.f;
            float r = sigf(ir + hr);
            float z = sigf(iz + hz);
            float nn = tanhf(in_ + r * hn);
            float hx = (1.f - z) * nn + z * hp;
            if (n < N_NODES) out_h[(size_t)n * 64 + j] = hx;
            hnS[nd * 68 + j] = hx;
        }
        __syncthreads();

        if (tid < 192) {
            int nd = tid / 3, k = tid % 3;
            int n = n0 + nd;
            if (n < N_NODES) {
                float a = boS[k];
                #pragma unroll
                for (int j = 0; j < 64; j++) a += hnS[nd * 68 + j] * woS[j * 3 + k];
                out_p[(size_t)n * 3 + k] = a;
            }
        }
        __syncthreads();
    }
}

extern "C" void kernel_launch(void* const* d_in, const int* in_sizes, int n_in,
                              void* d_out, int out_size) {
    const float* x       = (const float*)d_in[0];
    const float* h_prev  = (const float*)d_in[1];
    const int* en        = (const int*)d_in[2];
    const int* eh        = (const int*)d_in[3];
    const int* ea        = (const int*)d_in[4];
    const float* W_conv  = (const float*)d_in[5];
    const float* b_conv  = (const float*)d_in[6];
    const float* W_mix   = (const float*)d_in[7];
    const float* b_mix   = (const float*)d_in[8];
    const float* W_ih    = (const float*)d_in[9];
    const float* W_hh    = (const float*)d_in[10];
    const float* b_ih    = (const float*)d_in[11];
    const float* b_hh    = (const float*)d_in[12];
    const float* W_out   = (const float*)d_in[13];
    const float* b_out   = (const float*)d_in[14];
    float* out = (float*)d_out;
    float* out_h = out;
    float* out_p = out + (size_t)N_NODES * 64;

    static const int mix_smem = (8320 + 8192 + 64 + 128) * 4;
    static const int gru_smem = 34628 * 4;
    cudaFuncSetAttribute(k_mix, cudaFuncAttributeMaxDynamicSharedMemorySize, mix_smem);
    cudaFuncSetAttribute(k_gru_mma, cudaFuncAttributeMaxDynamicSharedMemorySize, gru_smem);

    k_zero_hist<<<(SB + 255) / 256, 256>>>();
    k_hist<<<(NE + 255) / 256, 256>>>(en, eh, ea);
    k_scan_local<<<NBB, 256>>>(0);
    k_scan_local<<<NBD, 256>>>(1);
    k_scan_tops<<<1, 512>>>(0);
    k_scan_tops<<<1, 512>>>(1);
    k_scan_add<<<(SB + 255) / 256, 256>>>(0);
    k_scan_add<<<(SD + 255) / 256, 256>>>(1);
    k_place<<<(NE + 255) / 256, 256>>>(en, eh, ea);

    k_xw<<<N_NODES / 8, 128>>>(x, W_conv);

    k_gather1<<<(SB * 8 + 255) / 256, 256>>>();
    k_gather2<<<(SD * 8 + 255) / 256, 256>>>();

    k_mix<<<(N_NODES + 63) / 64, 256, mix_smem>>>(W_mix, b_mix, b_conv);
    k_gru_mma<<<152, 256, gru_smem>>>(h_prev, W_ih, W_hh, b_ih, b_hh,
                                      W_out, b_out, out_h, out_p);
}

// round 9
// speedup vs baseline: 1.2075x; 1.0100x over previous
#include <cuda_runtime.h>
#include <cuda_fp16.h>
#include <cstdint>

#define N_NODES 100000
#define M_HE    200000
#define NE      2000000
#define IN_F    16
#define HID     64
#define NT      2

#define SB (NT * M_HE)     // 400000
#define SD (NT * N_NODES)  // 200000
#define NBB ((SB + 1023) / 1024)   // 391
#define NBD ((SD + 1023) / 1024)   // 196
#define TILES ((N_NODES + 63) / 64)  // 1563
#define XW_BLOCKS (N_NODES / 16)     // 6250
#define HIST_BLOCKS ((NE + 255) / 256)

// ---------------- scratch ----------------
__device__ __align__(16) __half g_xw_h[(size_t)N_NODES * 128];
__device__ __align__(16) __half g_efeat_h[(size_t)M_HE * 128];
__device__ __align__(16) float  g_acc[(size_t)N_NODES * 128];
__device__ __align__(16) float  g_h[(size_t)N_NODES * HID];
__device__ int g_hB[SB], g_hD[SD];
__device__ int g_offB[SB + 1], g_offD[SD + 1];
__device__ int g_curB[SB], g_curD[SD];
__device__ unsigned long long g_flagB[NBB], g_flagD[NBD];
__device__ int g_idxB[NE];
__device__ int g_idxD[NE];

// ---------------- launch 0: xw projection + histogram + flag zero ----------------
__global__ void k_xw_hist(const float* __restrict__ x, const float* __restrict__ Wc,
                          const int* __restrict__ en, const int* __restrict__ eh,
                          const int* __restrict__ ea) {
    if (blockIdx.x < XW_BLOCKS) {
        __shared__ float Ws[NT * IN_F * HID];   // 2048
        __shared__ float xs[16 * IN_F];         // 256
        int tid = threadIdx.x;
        int n0 = blockIdx.x * 16;
        for (int i = tid; i < NT * IN_F * HID; i += 256) Ws[i] = Wc[i];
        xs[tid] = x[(size_t)n0 * IN_F + tid];
        __syncthreads();
        int c = tid & 127;
        int hf = tid >> 7;
        int t = c >> 6, cc = c & 63;
        const float* w = &Ws[t * (IN_F * HID) + cc];
        #pragma unroll
        for (int nd = 0; nd < 8; nd++) {
            int node = n0 + hf * 8 + nd;
            float a = 0.f;
            #pragma unroll
            for (int k = 0; k < IN_F; k++) a += xs[(hf * 8 + nd) * IN_F + k] * w[k * HID];
            float a_hi = __shfl_down_sync(0xffffffffu, a, 1);
            if ((c & 1) == 0) {
                __half2 hv = __floats2half2_rn(a, a_hi);
                ((__half2*)g_xw_h)[((size_t)node * 128 + c) >> 1] = hv;
            }
        }
    } else {
        int hb = blockIdx.x - XW_BLOCKS;
        if (hb == 0) {  // zero lookback flags for this replay
            int tid = threadIdx.x;
            if (tid < NBB) g_flagB[tid] = 0ull;
            if (tid < NBD) g_flagD[tid] = 0ull;
        }
        int i = hb * 256 + threadIdx.x;
        if (i >= NE) return;
        int t = ea[i];
        atomicAdd(&g_hB[t * M_HE + eh[i]], 1);
        atomicAdd(&g_hD[t * N_NODES + en[i]], 1);
    }
}

// Wait: hb==0 block also zeroes flags (NBB=391 > 256). Handle with loop below instead.

// ---------------- launch 1: single-pass scan (decoupled lookback) ----------------
// grid = NBB + NBD, 256 threads. Blocks [0,NBB) = chain B, [NBB,..) = chain D.
// Reads hist, zeroes it, writes global exclusive offsets + cursors + sentinel.
__global__ void k_scan() {
    int b = blockIdx.x;
    bool isD = (b >= NBB);
    int cb = isD ? b - NBB : b;
    const int n = isD ? SD : SB;
    const int nb = isD ? NBD : NBB;
    int* hist = isD ? g_hD : g_hB;
    int* out  = isD ? g_offD : g_offB;
    int* cur  = isD ? g_curD : g_curB;
    volatile unsigned long long* flags = isD ? g_flagD : g_flagB;

    int tid = threadIdx.x;
    int base = cb * 1024 + tid * 4;
    int v0 = (base + 0 < n) ? hist[base + 0] : 0;
    int v1 = (base + 1 < n) ? hist[base + 1] : 0;
    int v2 = (base + 2 < n) ? hist[base + 2] : 0;
    int v3 = (base + 3 < n) ? hist[base + 3] : 0;
    // zero histogram for next replay (same thread owns these elements)
    if (base + 0 < n) hist[base + 0] = 0;
    if (base + 1 < n) hist[base + 1] = 0;
    if (base + 2 < n) hist[base + 2] = 0;
    if (base + 3 < n) hist[base + 3] = 0;
    int s = v0 + v1 + v2 + v3;
    __shared__ int sh[256];
    __shared__ int s_prev;
    sh[tid] = s;
    __syncthreads();
    for (int d = 1; d < 256; d <<= 1) {
        int v = (tid >= d) ? sh[tid - d] : 0;
        __syncthreads();
        sh[tid] += v;
        __syncthreads();
    }
    int excl = sh[tid] - s;

    if (tid == 255) {
        int total = excl + s;   // block aggregate
        int prev = 0;
        if (cb == 0) {
            flags[0] = (2ull << 62) | (unsigned long long)(unsigned)total;
        } else {
            flags[cb] = (1ull << 62) | (unsigned long long)(unsigned)total;
            for (int p = cb - 1; p >= 0; p--) {
                unsigned long long f;
                do { f = flags[p]; } while ((f >> 62) == 0ull);
                prev += (int)(unsigned)(f & 0xffffffffull);
                if ((f >> 62) == 2ull) break;
            }
            flags[cb] = (2ull << 62) | (unsigned long long)(unsigned)(prev + total);
        }
        s_prev = prev;
    }
    __syncthreads();
    int p0 = s_prev + excl;
    if (base + 0 < n) { out[base + 0] = p0;                cur[base + 0] = p0; }
    if (base + 1 < n) { out[base + 1] = p0 + v0;           cur[base + 1] = p0 + v0; }
    if (base + 2 < n) { out[base + 2] = p0 + v0 + v1;      cur[base + 2] = p0 + v0 + v1; }
    if (base + 3 < n) { out[base + 3] = p0 + v0 + v1 + v2; cur[base + 3] = p0 + v0 + v1 + v2; }
    if (tid == 0 && cb == nb - 1) out[n] = NE;   // sentinel
}

// ---------------- launch 2: placement ----------------
__global__ void k_place(const int* __restrict__ en, const int* __restrict__ eh,
                        const int* __restrict__ ea) {
    int i = blockIdx.x * blockDim.x + threadIdx.x;
    if (i >= NE) return;
    int t = ea[i], n = en[i], he = eh[i];
    int pb = atomicAdd(&g_curB[t * M_HE + he], 1);
    g_idxB[pb] = n;
    int pd = atomicAdd(&g_curD[t * N_NODES + n], 1);
    g_idxD[pd] = he;
}

__device__ __forceinline__ void accum8(float* s, uint4 v) {
    const __half2* h = (const __half2*)&v;
    #pragma unroll
    for (int i = 0; i < 4; i++) {
        float2 f = __half22float2(h[i]);
        s[2 * i]     += f.x;
        s[2 * i + 1] += f.y;
    }
}

// ---------------- launch 3: gather 1 ----------------
__global__ void k_gather1() {
    int idx = blockIdx.x * blockDim.x + threadIdx.x;
    int r = idx >> 3, q = idx & 7;
    if (r >= SB) return;
    int t = (r >= M_HE) ? 1 : 0;
    int he = r - t * M_HE;
    int start = g_offB[r];
    int cnt = g_offB[r + 1] - start;
    const uint4* xw4 = (const uint4*)g_xw_h;
    int off = t * 8 + q;
    float s[8] = {0.f, 0.f, 0.f, 0.f, 0.f, 0.f, 0.f, 0.f};
    int j = 0;
    for (; j + 4 <= cnt; j += 4) {
        int n0 = __ldg(&g_idxB[start + j]);
        int n1 = __ldg(&g_idxB[start + j + 1]);
        int n2 = __ldg(&g_idxB[start + j + 2]);
        int n3 = __ldg(&g_idxB[start + j + 3]);
        uint4 v0 = xw4[(size_t)n0 * 16 + off];
        uint4 v1 = xw4[(size_t)n1 * 16 + off];
        uint4 v2 = xw4[(size_t)n2 * 16 + off];
        uint4 v3 = xw4[(size_t)n3 * 16 + off];
        accum8(s, v0); accum8(s, v1); accum8(s, v2); accum8(s, v3);
    }
    for (; j < cnt; j++) {
        int n = __ldg(&g_idxB[start + j]);
        accum8(s, xw4[(size_t)n * 16 + off]);
    }
    float binv = (cnt > 0) ? (1.f / (float)cnt) : 0.f;
    uint4 outv;
    __half2* oh = (__half2*)&outv;
    #pragma unroll
    for (int i = 0; i < 4; i++)
        oh[i] = __floats2half2_rn(s[2 * i] * binv, s[2 * i + 1] * binv);
    ((uint4*)g_efeat_h)[(size_t)he * 16 + t * 8 + q] = outv;
}

// ---------------- launch 4: gather 2 ----------------
__global__ void k_gather2() {
    int idx = blockIdx.x * blockDim.x + threadIdx.x;
    int r = idx >> 3, q = idx & 7;
    if (r >= SD) return;
    int t = (r >= N_NODES) ? 1 : 0;
    int n = r - t * N_NODES;
    int start = g_offD[r];
    int cnt = g_offD[r + 1] - start;
    const uint4* ef4 = (const uint4*)g_efeat_h;
    int off = t * 8 + q;
    float s[8] = {0.f, 0.f, 0.f, 0.f, 0.f, 0.f, 0.f, 0.f};
    int j = 0;
    for (; j + 4 <= cnt; j += 4) {
        int h0 = __ldg(&g_idxD[start + j]);
        int h1 = __ldg(&g_idxD[start + j + 1]);
        int h2 = __ldg(&g_idxD[start + j + 2]);
        int h3 = __ldg(&g_idxD[start + j + 3]);
        uint4 v0 = ef4[(size_t)h0 * 16 + off];
        uint4 v1 = ef4[(size_t)h1 * 16 + off];
        uint4 v2 = ef4[(size_t)h2 * 16 + off];
        uint4 v3 = ef4[(size_t)h3 * 16 + off];
        accum8(s, v0); accum8(s, v1); accum8(s, v2); accum8(s, v3);
    }
    for (; j < cnt; j++) {
        int he = __ldg(&g_idxD[start + j]);
        accum8(s, ef4[(size_t)he * 16 + off]);
    }
    float dinv = (cnt > 0) ? (1.f / (float)cnt) : 0.f;
    float4 o0 = make_float4(s[0] * dinv, s[1] * dinv, s[2] * dinv, s[3] * dinv);
    float4 o1 = make_float4(s[4] * dinv, s[5] * dinv, s[6] * dinv, s[7] * dinv);
    ((float4*)g_acc)[(size_t)n * 32 + t * 16 + q * 2]     = o0;
    ((float4*)g_acc)[(size_t)n * 32 + t * 16 + q * 2 + 1] = o1;
}

#define FMA2(d, a, b) asm("fma.rn.f32x2 %0, %1, %2, %0;" : "+l"(d) : "l"(a), "l"(b))

__device__ __forceinline__ float hsum2(uint64_t v) {
    float lo, hi;
    asm("mov.b64 {%0,%1}, %2;" : "=f"(lo), "=f"(hi) : "l"(v));
    return lo + hi;
}

// ---------------- launch 5: mix ----------------
__global__ void k_mix(const float* __restrict__ Wmix, const float* __restrict__ bmix,
                      const float* __restrict__ bconv) {
    extern __shared__ float sm[];
    float* u_s  = sm;                 // 64 * 130
    float* Wp   = sm + 8320;          // 8192
    float* bm_s = Wp + 8192;          // 64
    float* bc_s = bm_s + 64;          // 128
    int tid = threadIdx.x;
    int n0 = blockIdx.x * 64;

    for (int i = tid; i < 4096; i += 256) {
        int k2 = i >> 6, c = i & 63;
        Wp[i * 2]     = Wmix[(2 * k2) * 64 + c];
        Wp[i * 2 + 1] = Wmix[(2 * k2 + 1) * 64 + c];
    }
    if (tid < 64)  bm_s[tid] = bmix[tid];
    if (tid < 128) bc_s[tid] = bconv[tid];
    __syncthreads();

    for (int idx = tid; idx < 64 * 128; idx += 256) {
        int nd = idx >> 7, c = idx & 127;
        int n = n0 + nd;
        float u = 0.f;
        if (n < N_NODES) u = g_acc[(size_t)n * 128 + c] + bc_s[c];
        u_s[nd * 130 + c] = u;
    }
    __syncthreads();

    int colg = tid & 15;
    int nodeg = tid >> 4;
    uint64_t acc2[4][4];
    #pragma unroll
    for (int i = 0; i < 4; i++)
        #pragma unroll
        for (int j = 0; j < 4; j++) acc2[i][j] = 0ull;

    #pragma unroll 4
    for (int k2 = 0; k2 < 64; k2++) {
        uint64_t w[4];
        #pragma unroll
        for (int j = 0; j < 4; j++)
            w[j] = *(const uint64_t*)&Wp[(k2 * 64 + colg + 16 * j) * 2];
        #pragma unroll
        for (int i = 0; i < 4; i++) {
            uint64_t uv = *(const uint64_t*)&u_s[(nodeg * 4 + i) * 130 + k2 * 2];
            #pragma unroll
            for (int j = 0; j < 4; j++) FMA2(acc2[i][j], uv, w[j]);
        }
    }

    #pragma unroll
    for (int i = 0; i < 4; i++) {
        int n = n0 + nodeg * 4 + i;
        if (n < N_NODES) {
            #pragma unroll
            for (int j = 0; j < 4; j++) {
                int col = colg + 16 * j;
                float h = hsum2(acc2[i][j]) + bm_s[col];
                g_h[(size_t)n * 64 + col] = fmaxf(h, 0.f);
            }
        }
    }
}

__device__ __forceinline__ float sigf(float x) { return 1.f / (1.f + expf(-x)); }

#define MMA16816(c0, c1, c2, c3, a0, a1, a2, a3, b0, b1) \
    asm volatile("mma.sync.aligned.m16n8k16.row.col.f32.f16.f16.f32 " \
                 "{%0,%1,%2,%3}, {%4,%5,%6,%7}, {%8,%9}, {%0,%1,%2,%3};" \
                 : "+f"(c0), "+f"(c1), "+f"(c2), "+f"(c3) \
                 : "r"(a0), "r"(a1), "r"(a2), "r"(a3), "r"(b0), "r"(b1))

// ---------------- launch 6: GRU via fp16 mma.sync (persistent) ----------------
__global__ __launch_bounds__(256, 1)
void k_gru_mma(const float* __restrict__ hprev,
               const float* __restrict__ Wih, const float* __restrict__ Whh,
               const float* __restrict__ bih, const float* __restrict__ bhh,
               const float* __restrict__ Wout, const float* __restrict__ bout,
               float* __restrict__ out_h, float* __restrict__ out_p) {
    extern __shared__ float smf[];
    float*  stage = smf;                          // [2][64][196]
    __half* Wih16 = (__half*)smf;                 // [192][72]
    __half* Whh16 = Wih16 + 192 * 72;             // [192][72]
    __half* h16   = (__half*)(smf + 25088);       // [64][72]
    __half* hp16  = h16 + 64 * 72;                // [64][72]
    float*  hnS   = smf + 29696;                  // [64][68]
    float*  bihS  = smf + 34048;
    float*  bhhS  = bihS + 192;
    float*  woS   = bhhS + 192;
    float*  boS   = woS + 192;

    int tid = threadIdx.x;
    int lane = tid & 31;
    int wrp = tid >> 5;
    int g = lane >> 2;
    int t = lane & 3;
    int cbase = wrp * 24;

    if (tid < 192) {
        bihS[tid] = bih[tid];
        bhhS[tid] = bhh[tid];
        int j = tid / 3, k = tid % 3;
        woS[tid] = Wout[j * 64 + k];
    }
    if (tid < 3) boS[tid] = bout[tid];

    for (int i = tid; i < 192 * 64; i += 256) {
        int r = i >> 6, k = i & 63;
        Wih16[r * 72 + k] = __float2half(Wih[i]);
        Whh16[r * 72 + k] = __float2half(Whh[i]);
    }
    __syncthreads();

    uint32_t Bi[3][4][2], Bh[3][4][2];
    #pragma unroll
    for (int nt = 0; nt < 3; nt++) {
        int n = cbase + nt * 8 + g;
        #pragma unroll
        for (int ks = 0; ks < 4; ks++) {
            Bi[nt][ks][0] = *(const uint32_t*)&Wih16[n * 72 + ks * 16 + 2 * t];
            Bi[nt][ks][1] = *(const uint32_t*)&Wih16[n * 72 + ks * 16 + 2 * t + 8];
            Bh[nt][ks][0] = *(const uint32_t*)&Whh16[n * 72 + ks * 16 + 2 * t];
            Bh[nt][ks][1] = *(const uint32_t*)&Whh16[n * 72 + ks * 16 + 2 * t + 8];
        }
    }
    __syncthreads();

    for (int tile = blockIdx.x; tile < TILES; tile += gridDim.x) {
        int n0 = tile * 64;
        for (int i = tid; i < 64 * 64; i += 256) {
            int nd = i >> 6, k = i & 63;
            int n = n0 + nd;
            float hv = 0.f, pv = 0.f;
            if (n < N_NODES) {
                hv = g_h[(size_t)n * 64 + k];
                pv = hprev[(size_t)n * 64 + k];
            }
            h16[nd * 72 + k]  = __float2half(hv);
            hp16[nd * 72 + k] = __float2half(pv);
        }
        __syncthreads();

        float acc[2][4][3][4];
        #pragma unroll
        for (int mt = 0; mt < 2; mt++)
            #pragma unroll
            for (int m = 0; m < 4; m++)
                #pragma unroll
                for (int nt = 0; nt < 3; nt++)
                    #pragma unroll
                    for (int c = 0; c < 4; c++) acc[mt][m][nt][c] = 0.f;

        #pragma unroll
        for (int mt = 0; mt < 2; mt++) {
            const __half* A = mt ? hp16 : h16;
            #pragma unroll
            for (int ks = 0; ks < 4; ks++) {
                #pragma unroll
                for (int m = 0; m < 4; m++) {
                    int row = m * 16 + g;
                    int ko = ks * 16 + 2 * t;
                    uint32_t a0 = *(const uint32_t*)&A[row * 72 + ko];
                    uint32_t a1 = *(const uint32_t*)&A[(row + 8) * 72 + ko];
                    uint32_t a2 = *(const uint32_t*)&A[row * 72 + ko + 8];
                    uint32_t a3 = *(const uint32_t*)&A[(row + 8) * 72 + ko + 8];
                    #pragma unroll
                    for (int nt = 0; nt < 3; nt++) {
                        if (mt == 0) {
                            MMA16816(acc[0][m][nt][0], acc[0][m][nt][1],
                                     acc[0][m][nt][2], acc[0][m][nt][3],
                                     a0, a1, a2, a3, Bi[nt][ks][0], Bi[nt][ks][1]);
                        } else {
                            MMA16816(acc[1][m][nt][0], acc[1][m][nt][1],
                                     acc[1][m][nt][2], acc[1][m][nt][3],
                                     a0, a1, a2, a3, Bh[nt][ks][0], Bh[nt][ks][1]);
                        }
                    }
                }
            }
        }

        #pragma unroll
        for (int mt = 0; mt < 2; mt++) {
            float* st = stage + mt * 12544;
            #pragma unroll
            for (int m = 0; m < 4; m++) {
                int row = m * 16 + g;
                #pragma unroll
                for (int nt = 0; nt < 3; nt++) {
                    int col = cbase + nt * 8 + 2 * t;
                    *(float2*)&st[row * 196 + col] =
                        make_float2(acc[mt][m][nt][0], acc[mt][m][nt][1]);
                    *(float2*)&st[(row + 8) * 196 + col] =
                        make_float2(acc[mt][m][nt][2], acc[mt][m][nt][3]);
                }
            }
        }
        __syncthreads();

        for (int i = tid; i < 64 * 64; i += 256) {
            int nd = i >> 6, j = i & 63;
            int n = n0 + nd;
            float ir = stage[nd * 196 + j]        + bihS[j];
            float iz = stage[nd * 196 + j + 64]   + bihS[64 + j];
            float in_ = stage[nd * 196 + j + 128] + bihS[128 + j];
            float hr = stage[12544 + nd * 196 + j]        + bhhS[j];
            float hz = stage[12544 + nd * 196 + j + 64]   + bhhS[64 + j];
            float hn = stage[12544 + nd * 196 + j + 128]  + bhhS[128 + j];
            float hp = (n < N_NODES) ? hprev[(size_t)n * 64 + j] : 0.f;
            float r = sigf(ir + hr);
            float z = sigf(iz + hz);
            float nn = tanhf(in_ + r * hn);
            float hx = (1.f - z) * nn + z * hp;
            if (n < N_NODES) out_h[(size_t)n * 64 + j] = hx;
            hnS[nd * 68 + j] = hx;
        }
        __syncthreads();

        if (tid < 192) {
            int nd = tid / 3, k = tid % 3;
            int n = n0 + nd;
            if (n < N_NODES) {
                float a = boS[k];
                #pragma unroll
                for (int j = 0; j < 64; j++) a += hnS[nd * 68 + j] * woS[j * 3 + k];
                out_p[(size_t)n * 3 + k] = a;
            }
        }
        __syncthreads();
    }
}

extern "C" void kernel_launch(void* const* d_in, const int* in_sizes, int n_in,
                              void* d_out, int out_size) {
    const float* x       = (const float*)d_in[0];
    const float* h_prev  = (const float*)d_in[1];
    const int* en        = (const int*)d_in[2];
    const int* eh        = (const int*)d_in[3];
    const int* ea        = (const int*)d_in[4];
    const float* W_conv  = (const float*)d_in[5];
    const float* b_conv  = (const float*)d_in[6];
    const float* W_mix   = (const float*)d_in[7];
    const float* b_mix   = (const float*)d_in[8];
    const float* W_ih    = (const float*)d_in[9];
    const float* W_hh    = (const float*)d_in[10];
    const float* b_ih    = (const float*)d_in[11];
    const float* b_hh    = (const float*)d_in[12];
    const float* W_out   = (const float*)d_in[13];
    const float* b_out   = (const float*)d_in[14];
    float* out = (float*)d_out;
    float* out_h = out;
    float* out_p = out + (size_t)N_NODES * 64;

    static const int mix_smem = (8320 + 8192 + 64 + 128) * 4;
    static const int gru_smem = 34628 * 4;
    cudaFuncSetAttribute(k_mix, cudaFuncAttributeMaxDynamicSharedMemorySize, mix_smem);
    cudaFuncSetAttribute(k_gru_mma, cudaFuncAttributeMaxDynamicSharedMemorySize, gru_smem);

    k_xw_hist<<<XW_BLOCKS + HIST_BLOCKS, 256>>>(x, W_conv, en, eh, ea);  // 0
    k_scan<<<NBB + NBD, 256>>>();                                         // 1
    k_place<<<(NE + 255) / 256, 256>>>(en, eh, ea);                       // 2
    k_gather1<<<(SB * 8 + 255) / 256, 256>>>();                           // 3 <- ncu
    k_gather2<<<(SD * 8 + 255) / 256, 256>>>();                           // 4
    k_mix<<<(N_NODES + 63) / 64, 256, mix_smem>>>(W_mix, b_mix, b_conv);  // 5
    k_gru_mma<<<152, 256, gru_smem>>>(h_prev, W_ih, W_hh, b_ih, b_hh,     // 6
                                      W_out, b_out, out_h, out_p);
}

// round 10
// speedup vs baseline: 1.3516x; 1.1193x over previous
#include <cuda_runtime.h>
#include <cuda_fp16.h>
#include <cstdint>

#define N_NODES 100000
#define M_HE    200000
#define NE      2000000
#define IN_F    16
#define HID     64
#define NT      2

#define SB (NT * M_HE)     // 400000
#define SD (NT * N_NODES)  // 200000
#define NBB ((SB + 1023) / 1024)   // 391
#define NBD ((SD + 1023) / 1024)   // 196
#define TILES ((N_NODES + 63) / 64)  // 1563
#define XW_BLOCKS (N_NODES / 16)     // 6250
#define HIST_BLOCKS ((NE + 255) / 256)

// ---------------- scratch ----------------
__device__ __align__(16) __half g_xw_h[(size_t)N_NODES * 128];
__device__ __align__(16) __half g_efeat_h[(size_t)M_HE * 128];
__device__ __align__(16) __half g_u_h[(size_t)N_NODES * 128];   // u = acc*dinv + bconv (fp16)
__device__ __align__(16) __half g_h_h[(size_t)N_NODES * HID];   // mix output (fp16)
__device__ int g_hB[SB], g_hD[SD];
__device__ int g_offB[SB + 1], g_offD[SD + 1];
__device__ int g_curB[SB], g_curD[SD];
__device__ unsigned long long g_flagB[NBB], g_flagD[NBD];
__device__ int g_idxB[NE];
__device__ int g_idxD[NE];

// ---------------- launch 0: xw projection + histogram + flag zero ----------------
__global__ void k_xw_hist(const float* __restrict__ x, const float* __restrict__ Wc,
                          const int* __restrict__ en, const int* __restrict__ eh,
                          const int* __restrict__ ea) {
    if (blockIdx.x < XW_BLOCKS) {
        __shared__ float Ws[NT * IN_F * HID];
        __shared__ float xs[16 * IN_F];
        int tid = threadIdx.x;
        int n0 = blockIdx.x * 16;
        for (int i = tid; i < NT * IN_F * HID; i += 256) Ws[i] = Wc[i];
        xs[tid] = x[(size_t)n0 * IN_F + tid];
        __syncthreads();
        int c = tid & 127;
        int hf = tid >> 7;
        int t = c >> 6, cc = c & 63;
        const float* w = &Ws[t * (IN_F * HID) + cc];
        #pragma unroll
        for (int nd = 0; nd < 8; nd++) {
            int node = n0 + hf * 8 + nd;
            float a = 0.f;
            #pragma unroll
            for (int k = 0; k < IN_F; k++) a += xs[(hf * 8 + nd) * IN_F + k] * w[k * HID];
            float a_hi = __shfl_down_sync(0xffffffffu, a, 1);
            if ((c & 1) == 0) {
                __half2 hv = __floats2half2_rn(a, a_hi);
                ((__half2*)g_xw_h)[((size_t)node * 128 + c) >> 1] = hv;
            }
        }
    } else {
        int hb = blockIdx.x - XW_BLOCKS;
        if (hb == 0) {
            for (int f = threadIdx.x; f < NBB; f += 256) g_flagB[f] = 0ull;
            for (int f = threadIdx.x; f < NBD; f += 256) g_flagD[f] = 0ull;
        }
        int i = hb * 256 + threadIdx.x;
        if (i >= NE) return;
        int t = ea[i];
        atomicAdd(&g_hB[t * M_HE + eh[i]], 1);
        atomicAdd(&g_hD[t * N_NODES + en[i]], 1);
    }
}

// ---------------- launch 1: single-pass scan (decoupled lookback) ----------------
__global__ void k_scan() {
    int b = blockIdx.x;
    bool isD = (b >= NBB);
    int cb = isD ? b - NBB : b;
    const int n = isD ? SD : SB;
    const int nb = isD ? NBD : NBB;
    int* hist = isD ? g_hD : g_hB;
    int* out  = isD ? g_offD : g_offB;
    int* cur  = isD ? g_curD : g_curB;
    volatile unsigned long long* flags = isD ? g_flagD : g_flagB;

    int tid = threadIdx.x;
    int base = cb * 1024 + tid * 4;
    int v0 = (base + 0 < n) ? hist[base + 0] : 0;
    int v1 = (base + 1 < n) ? hist[base + 1] : 0;
    int v2 = (base + 2 < n) ? hist[base + 2] : 0;
    int v3 = (base + 3 < n) ? hist[base + 3] : 0;
    if (base + 0 < n) hist[base + 0] = 0;
    if (base + 1 < n) hist[base + 1] = 0;
    if (base + 2 < n) hist[base + 2] = 0;
    if (base + 3 < n) hist[base + 3] = 0;
    int s = v0 + v1 + v2 + v3;
    __shared__ int sh[256];
    __shared__ int s_prev;
    sh[tid] = s;
    __syncthreads();
    for (int d = 1; d < 256; d <<= 1) {
        int v = (tid >= d) ? sh[tid - d] : 0;
        __syncthreads();
        sh[tid] += v;
        __syncthreads();
    }
    int excl = sh[tid] - s;

    if (tid == 255) {
        int total = excl + s;
        int prev = 0;
        if (cb == 0) {
            flags[0] = (2ull << 62) | (unsigned long long)(unsigned)total;
        } else {
            flags[cb] = (1ull << 62) | (unsigned long long)(unsigned)total;
            for (int p = cb - 1; p >= 0; p--) {
                unsigned long long f;
                do { f = flags[p]; } while ((f >> 62) == 0ull);
                prev += (int)(unsigned)(f & 0xffffffffull);
                if ((f >> 62) == 2ull) break;
            }
            flags[cb] = (2ull << 62) | (unsigned long long)(unsigned)(prev + total);
        }
        s_prev = prev;
    }
    __syncthreads();
    int p0 = s_prev + excl;
    if (base + 0 < n) { out[base + 0] = p0;                cur[base + 0] = p0; }
    if (base + 1 < n) { out[base + 1] = p0 + v0;           cur[base + 1] = p0 + v0; }
    if (base + 2 < n) { out[base + 2] = p0 + v0 + v1;      cur[base + 2] = p0 + v0 + v1; }
    if (base + 3 < n) { out[base + 3] = p0 + v0 + v1 + v2; cur[base + 3] = p0 + v0 + v1 + v2; }
    if (tid == 0 && cb == nb - 1) out[n] = NE;
}

// ---------------- launch 2: placement ----------------
__global__ void k_place(const int* __restrict__ en, const int* __restrict__ eh,
                        const int* __restrict__ ea) {
    int i = blockIdx.x * blockDim.x + threadIdx.x;
    if (i >= NE) return;
    int t = ea[i], n = en[i], he = eh[i];
    int pb = atomicAdd(&g_curB[t * M_HE + he], 1);
    g_idxB[pb] = n;
    int pd = atomicAdd(&g_curD[t * N_NODES + n], 1);
    g_idxD[pd] = he;
}

__device__ __forceinline__ void accum8(float* s, uint4 v) {
    const __half2* h = (const __half2*)&v;
    #pragma unroll
    for (int i = 0; i < 4; i++) {
        float2 f = __half22float2(h[i]);
        s[2 * i]     += f.x;
        s[2 * i + 1] += f.y;
    }
}

// depth-2 fp16 pairwise reduce of 4 uint4s, fp32 accumulate once
__device__ __forceinline__ void accum4x(float* s, uint4 v0, uint4 v1, uint4 v2, uint4 v3) {
    const __half2* h0 = (const __half2*)&v0;
    const __half2* h1 = (const __half2*)&v1;
    const __half2* h2 = (const __half2*)&v2;
    const __half2* h3 = (const __half2*)&v3;
    #pragma unroll
    for (int i = 0; i < 4; i++) {
        __half2 ss = __hadd2(__hadd2(h0[i], h1[i]), __hadd2(h2[i], h3[i]));
        float2 f = __half22float2(ss);
        s[2 * i]     += f.x;
        s[2 * i + 1] += f.y;
    }
}

// ---------------- launch 3: gather 1 ----------------
__global__ void k_gather1() {
    int idx = blockIdx.x * blockDim.x + threadIdx.x;
    int r = idx >> 3, q = idx & 7;
    if (r >= SB) return;
    int t = (r >= M_HE) ? 1 : 0;
    int he = r - t * M_HE;
    int start = g_offB[r];
    int cnt = g_offB[r + 1] - start;
    const char* xwb = (const char*)g_xw_h + (unsigned)(t * 8 + q) * 16u;
    const int* ip = g_idxB + start;
    float s[8] = {0.f, 0.f, 0.f, 0.f, 0.f, 0.f, 0.f, 0.f};
    int j = 0;
    for (; j + 4 <= cnt; j += 4) {
        unsigned o0 = (unsigned)__ldg(ip + j)     * 256u;
        unsigned o1 = (unsigned)__ldg(ip + j + 1) * 256u;
        unsigned o2 = (unsigned)__ldg(ip + j + 2) * 256u;
        unsigned o3 = (unsigned)__ldg(ip + j + 3) * 256u;
        uint4 v0 = *(const uint4*)(xwb + o0);
        uint4 v1 = *(const uint4*)(xwb + o1);
        uint4 v2 = *(const uint4*)(xwb + o2);
        uint4 v3 = *(const uint4*)(xwb + o3);
        accum4x(s, v0, v1, v2, v3);
    }
    for (; j < cnt; j++) {
        unsigned o = (unsigned)__ldg(ip + j) * 256u;
        accum8(s, *(const uint4*)(xwb + o));
    }
    float binv = (cnt > 0) ? (1.f / (float)cnt) : 0.f;
    uint4 outv;
    __half2* oh = (__half2*)&outv;
    #pragma unroll
    for (int i = 0; i < 4; i++)
        oh[i] = __floats2half2_rn(s[2 * i] * binv, s[2 * i + 1] * binv);
    ((uint4*)g_efeat_h)[(size_t)he * 16 + t * 8 + q] = outv;
}

// ---------------- launch 4: gather 2 (fuses *dinv + b_conv, fp16 out) ----------------
__global__ void k_gather2(const float* __restrict__ bconv) {
    int idx = blockIdx.x * blockDim.x + threadIdx.x;
    int r = idx >> 3, q = idx & 7;
    if (r >= SD) return;
    int t = (r >= N_NODES) ? 1 : 0;
    int n = r - t * N_NODES;
    int start = g_offD[r];
    int cnt = g_offD[r + 1] - start;
    const char* efb = (const char*)g_efeat_h + (unsigned)(t * 8 + q) * 16u;
    const int* ip = g_idxD + start;
    float s[8] = {0.f, 0.f, 0.f, 0.f, 0.f, 0.f, 0.f, 0.f};
    int j = 0;
    for (; j + 4 <= cnt; j += 4) {
        unsigned o0 = (unsigned)__ldg(ip + j)     * 256u;
        unsigned o1 = (unsigned)__ldg(ip + j + 1) * 256u;
        unsigned o2 = (unsigned)__ldg(ip + j + 2) * 256u;
        unsigned o3 = (unsigned)__ldg(ip + j + 3) * 256u;
        uint4 v0 = *(const uint4*)(efb + o0);
        uint4 v1 = *(const uint4*)(efb + o1);
        uint4 v2 = *(const uint4*)(efb + o2);
        uint4 v3 = *(const uint4*)(efb + o3);
        accum4x(s, v0, v1, v2, v3);
    }
    for (; j < cnt; j++) {
        unsigned o = (unsigned)__ldg(ip + j) * 256u;
        accum8(s, *(const uint4*)(efb + o));
    }
    float dinv = (cnt > 0) ? (1.f / (float)cnt) : 0.f;
    int cbase = t * 64 + q * 8;
    float4 b0 = *(const float4*)(bconv + cbase);
    float4 b1 = *(const float4*)(bconv + cbase + 4);
    uint4 outv;
    __half2* oh = (__half2*)&outv;
    oh[0] = __floats2half2_rn(s[0] * dinv + b0.x, s[1] * dinv + b0.y);
    oh[1] = __floats2half2_rn(s[2] * dinv + b0.z, s[3] * dinv + b0.w);
    oh[2] = __floats2half2_rn(s[4] * dinv + b1.x, s[5] * dinv + b1.y);
    oh[3] = __floats2half2_rn(s[6] * dinv + b1.z, s[7] * dinv + b1.w);
    ((uint4*)g_u_h)[(size_t)n * 16 + t * 8 + q] = outv;
}

__device__ __forceinline__ float sigf(float x) { return 1.f / (1.f + expf(-x)); }

#define MMA16816(c0, c1, c2, c3, a0, a1, a2, a3, b0, b1) \
    asm volatile("mma.sync.aligned.m16n8k16.row.col.f32.f16.f16.f32 " \
                 "{%0,%1,%2,%3}, {%4,%5,%6,%7}, {%8,%9}, {%0,%1,%2,%3};" \
                 : "+f"(c0), "+f"(c1), "+f"(c2), "+f"(c3) \
                 : "r"(a0), "r"(a1), "r"(a2), "r"(a3), "r"(b0), "r"(b1))

// ---------------- launch 5: mix via MMA (persistent) ----------------
// smem: buf [64][136] halves (17408B) — Wmix^T during init, u16 during tiles.
__global__ __launch_bounds__(256, 1)
void k_mix_mma(const float* __restrict__ Wmix, const float* __restrict__ bmix,
               float* __restrict__ dummy_unused) {
    extern __shared__ __half sbuf[];
    __half* buf = sbuf;                        // [128 rows max][136] — WmixT uses 64 rows of 136
    int tid = threadIdx.x;
    int lane = tid & 31;
    int wrp = tid >> 5;
    int g = lane >> 2;
    int t = lane & 3;

    // stage Wmix^T [64][128] into buf with stride 136
    for (int i = tid; i < 64 * 128; i += 256) {
        int n = i >> 7, k = i & 127;
        buf[n * 136 + k] = __float2half(Wmix[k * 64 + n]);
    }
    __syncthreads();

    uint32_t Bm[8][2];
    {
        int n = wrp * 8 + g;
        #pragma unroll
        for (int ks = 0; ks < 8; ks++) {
            Bm[ks][0] = *(const uint32_t*)&buf[n * 136 + ks * 16 + 2 * t];
            Bm[ks][1] = *(const uint32_t*)&buf[n * 136 + ks * 16 + 2 * t + 8];
        }
    }
    int col = wrp * 8 + 2 * t;
    float bm0 = bmix[col], bm1 = bmix[col + 1];
    __syncthreads();   // WmixT dead; buf becomes u16

    for (int tile = blockIdx.x; tile < TILES; tile += gridDim.x) {
        int n0 = tile * 64;
        for (int i = tid; i < 1024; i += 256) {
            int nd = i >> 4, c8 = (i & 15) * 8;
            int n = n0 + nd;
            uint4 v = make_uint4(0u, 0u, 0u, 0u);
            if (n < N_NODES) v = ((const uint4*)g_u_h)[(size_t)n * 16 + (c8 >> 3)];
            *(uint4*)&buf[nd * 136 + c8] = v;
        }
        __syncthreads();

        float am[4][4];
        #pragma unroll
        for (int m = 0; m < 4; m++)
            #pragma unroll
            for (int c = 0; c < 4; c++) am[m][c] = 0.f;

        #pragma unroll
        for (int ks = 0; ks < 8; ks++) {
            #pragma unroll
            for (int m = 0; m < 4; m++) {
                int row = m * 16 + g;
                int ko = ks * 16 + 2 * t;
                uint32_t a0 = *(const uint32_t*)&buf[row * 136 + ko];
                uint32_t a1 = *(const uint32_t*)&buf[(row + 8) * 136 + ko];
                uint32_t a2 = *(const uint32_t*)&buf[row * 136 + ko + 8];
                uint32_t a3 = *(const uint32_t*)&buf[(row + 8) * 136 + ko + 8];
                MMA16816(am[m][0], am[m][1], am[m][2], am[m][3],
                         a0, a1, a2, a3, Bm[ks][0], Bm[ks][1]);
            }
        }

        #pragma unroll
        for (int m = 0; m < 4; m++) {
            int row = m * 16 + g;
            int na = n0 + row, nb = n0 + row + 8;
            if (na < N_NODES) {
                __half2 hv = __floats2half2_rn(fmaxf(am[m][0] + bm0, 0.f),
                                               fmaxf(am[m][1] + bm1, 0.f));
                *(__half2*)&g_h_h[(size_t)na * 64 + col] = hv;
            }
            if (nb < N_NODES) {
                __half2 hv = __floats2half2_rn(fmaxf(am[m][2] + bm0, 0.f),
                                               fmaxf(am[m][3] + bm1, 0.f));
                *(__half2*)&g_h_h[(size_t)nb * 64 + col] = hv;
            }
        }
        __syncthreads();
    }
}

// ---------------- launch 6: GRU via fp16 mma.sync (persistent) ----------------
__global__ __launch_bounds__(256, 1)
void k_gru_mma(const float* __restrict__ hprev,
               const float* __restrict__ Wih, const float* __restrict__ Whh,
               const float* __restrict__ bih, const float* __restrict__ bhh,
               const float* __restrict__ Wout, const float* __restrict__ bout,
               float* __restrict__ out_h, float* __restrict__ out_p) {
    extern __shared__ float smf[];
    float*  stage = smf;                          // [2][64][196]
    __half* Wih16 = (__half*)smf;                 // [192][72]
    __half* Whh16 = Wih16 + 192 * 72;             // [192][72]
    __half* h16   = (__half*)(smf + 25088);       // [64][72]
    __half* hp16  = h16 + 64 * 72;                // [64][72]
    float*  hnS   = smf + 29696;                  // [64][68]
    float*  bihS  = smf + 34048;
    float*  bhhS  = bihS + 192;
    float*  woS   = bhhS + 192;
    float*  boS   = woS + 192;

    int tid = threadIdx.x;
    int lane = tid & 31;
    int wrp = tid >> 5;
    int g = lane >> 2;
    int t = lane & 3;
    int cbase = wrp * 24;

    if (tid < 192) {
        bihS[tid] = bih[tid];
        bhhS[tid] = bhh[tid];
        int j = tid / 3, k = tid % 3;
        woS[tid] = Wout[j * 64 + k];
    }
    if (tid < 3) boS[tid] = bout[tid];

    for (int i = tid; i < 192 * 64; i += 256) {
        int r = i >> 6, k = i & 63;
        Wih16[r * 72 + k] = __float2half(Wih[i]);
        Whh16[r * 72 + k] = __float2half(Whh[i]);
    }
    __syncthreads();

    uint32_t Bi[3][4][2], Bh[3][4][2];
    #pragma unroll
    for (int nt = 0; nt < 3; nt++) {
        int n = cbase + nt * 8 + g;
        #pragma unroll
        for (int ks = 0; ks < 4; ks++) {
            Bi[nt][ks][0] = *(const uint32_t*)&Wih16[n * 72 + ks * 16 + 2 * t];
            Bi[nt][ks][1] = *(const uint32_t*)&Wih16[n * 72 + ks * 16 + 2 * t + 8];
            Bh[nt][ks][0] = *(const uint32_t*)&Whh16[n * 72 + ks * 16 + 2 * t];
            Bh[nt][ks][1] = *(const uint32_t*)&Whh16[n * 72 + ks * 16 + 2 * t + 8];
        }
    }
    __syncthreads();

    for (int tile = blockIdx.x; tile < TILES; tile += gridDim.x) {
        int n0 = tile * 64;
        // h16: direct uint4 copies from fp16 mix output
        for (int i = tid; i < 512; i += 256) {
            int nd = i >> 3, c8 = (i & 7) * 8;
            int n = n0 + nd;
            uint4 v = make_uint4(0u, 0u, 0u, 0u);
            if (n < N_NODES) v = ((const uint4*)g_h_h)[(size_t)n * 8 + (c8 >> 3)];
            *(uint4*)&h16[nd * 72 + c8] = v;
        }
        for (int i = tid; i < 64 * 64; i += 256) {
            int nd = i >> 6, k = i & 63;
            int n = n0 + nd;
            float pv = (n < N_NODES) ? hprev[(size_t)n * 64 + k] : 0.f;
            hp16[nd * 72 + k] = __float2half(pv);
        }
        __syncthreads();

        float acc[2][4][3][4];
        #pragma unroll
        for (int mt = 0; mt < 2; mt++)
            #pragma unroll
            for (int m = 0; m < 4; m++)
                #pragma unroll
                for (int nt = 0; nt < 3; nt++)
                    #pragma unroll
                    for (int c = 0; c < 4; c++) acc[mt][m][nt][c] = 0.f;

        #pragma unroll
        for (int mt = 0; mt < 2; mt++) {
            const __half* A = mt ? hp16 : h16;
            #pragma unroll
            for (int ks = 0; ks < 4; ks++) {
                #pragma unroll
                for (int m = 0; m < 4; m++) {
                    int row = m * 16 + g;
                    int ko = ks * 16 + 2 * t;
                    uint32_t a0 = *(const uint32_t*)&A[row * 72 + ko];
                    uint32_t a1 = *(const uint32_t*)&A[(row + 8) * 72 + ko];
                    uint32_t a2 = *(const uint32_t*)&A[row * 72 + ko + 8];
                    uint32_t a3 = *(const uint32_t*)&A[(row + 8) * 72 + ko + 8];
                    #pragma unroll
                    for (int nt = 0; nt < 3; nt++) {
                        if (mt == 0) {
                            MMA16816(acc[0][m][nt][0], acc[0][m][nt][1],
                                     acc[0][m][nt][2], acc[0][m][nt][3],
                                     a0, a1, a2, a3, Bi[nt][ks][0], Bi[nt][ks][1]);
                        } else {
                            MMA16816(acc[1][m][nt][0], acc[1][m][nt][1],
                                     acc[1][m][nt][2], acc[1][m][nt][3],
                                     a0, a1, a2, a3, Bh[nt][ks][0], Bh[nt][ks][1]);
                        }
                    }
                }
            }
        }

        #pragma unroll
        for (int mt = 0; mt < 2; mt++) {
            float* st = stage + mt * 12544;
            #pragma unroll
            for (int m = 0; m < 4; m++) {
                int row = m * 16 + g;
                #pragma unroll
                for (int nt = 0; nt < 3; nt++) {
                    int col = cbase + nt * 8 + 2 * t;
                    *(float2*)&st[row * 196 + col] =
                        make_float2(acc[mt][m][nt][0], acc[mt][m][nt][1]);
                    *(float2*)&st[(row + 8) * 196 + col] =
                        make_float2(acc[mt][m][nt][2], acc[mt][m][nt][3]);
                }
            }
        }
        __syncthreads();

        for (int i = tid; i < 64 * 64; i += 256) {
            int nd = i >> 6, j = i & 63;
            int n = n0 + nd;
            float ir = stage[nd * 196 + j]        + bihS[j];
            float iz = stage[nd * 196 + j + 64]   + bihS[64 + j];
            float in_ = stage[nd * 196 + j + 128] + bihS[128 + j];
            float hr = stage[12544 + nd * 196 + j]        + bhhS[j];
            float hz = stage[12544 + nd * 196 + j + 64]   + bhhS[64 + j];
            float hn = stage[12544 + nd * 196 + j + 128]  + bhhS[128 + j];
            float hp = (n < N_NODES) ? hprev[(size_t)n * 64 + j] : 0.f;
            float r = sigf(ir + hr);
            float z = sigf(iz + hz);
            float nn = tanhf(in_ + r * hn);
            float hx = (1.f - z) * nn + z * hp;
            if (n < N_NODES) out_h[(size_t)n * 64 + j] = hx;
            hnS[nd * 68 + j] = hx;
        }
        __syncthreads();

        if (tid < 192) {
            int nd = tid / 3, k = tid % 3;
            int n = n0 + nd;
            if (n < N_NODES) {
                float a = boS[k];
                #pragma unroll
                for (int j = 0; j < 64; j++) a += hnS[nd * 68 + j] * woS[j * 3 + k];
                out_p[(size_t)n * 3 + k] = a;
            }
        }
        __syncthreads();
    }
}

extern "C" void kernel_launch(void* const* d_in, const int* in_sizes, int n_in,
                              void* d_out, int out_size) {
    const float* x       = (const float*)d_in[0];
    const float* h_prev  = (const float*)d_in[1];
    const int* en        = (const int*)d_in[2];
    const int* eh        = (const int*)d_in[3];
    const int* ea        = (const int*)d_in[4];
    const float* W_conv  = (const float*)d_in[5];
    const float* b_conv  = (const float*)d_in[6];
    const float* W_mix   = (const float*)d_in[7];
    const float* b_mix   = (const float*)d_in[8];
    const float* W_ih    = (const float*)d_in[9];
    const float* W_hh    = (const float*)d_in[10];
    const float* b_ih    = (const float*)d_in[11];
    const float* b_hh    = (const float*)d_in[12];
    const float* W_out   = (const float*)d_in[13];
    const float* b_out   = (const float*)d_in[14];
    float* out = (float*)d_out;
    float* out_h = out;
    float* out_p = out + (size_t)N_NODES * 64;

    static const int mixmma_smem = 64 * 136 * 2 + 256;   // halves->bytes: 17408 + pad
    static const int gru_smem = 34628 * 4;
    cudaFuncSetAttribute(k_mix_mma, cudaFuncAttributeMaxDynamicSharedMemorySize, mixmma_smem);
    cudaFuncSetAttribute(k_gru_mma, cudaFuncAttributeMaxDynamicSharedMemorySize, gru_smem);

    k_xw_hist<<<XW_BLOCKS + HIST_BLOCKS, 256>>>(x, W_conv, en, eh, ea);   // 0
    k_scan<<<NBB + NBD, 256>>>();                                          // 1
    k_place<<<(NE + 255) / 256, 256>>>(en, eh, ea);                        // 2
    k_gather1<<<(SB * 8 + 255) / 256, 256>>>();                            // 3 <- ncu
    k_gather2<<<(SD * 8 + 255) / 256, 256>>>(b_conv);                      // 4
    k_mix_mma<<<152, 256, mixmma_smem>>>(W_mix, b_mix, nullptr);           // 5
    k_gru_mma<<<152, 256, gru_smem>>>(h_prev, W_ih, W_hh, b_ih, b_hh,      // 6
                                      W_out, b_out, out_h, out_p);
}